// round 12
// baseline (speedup 1.0000x reference)
#include <cuda_runtime.h>

#define NN 100000
#define EE 1600000
#define FIN 128
#define HH 64
#define OUTF 32
#define NB_SCAN 98   // ceil(100000/1024)

typedef unsigned long long u64;

// ---------------- scratch (device globals; no allocation) ----------------
// g_deg starts zero (static init); scan1_k re-zeroes after consuming.
__device__ int   g_deg[2 * NN];
__device__ float g_h[NN * HH];
__device__ float g_o[NN * HH];
__device__ float g_asrc[NN];
__device__ float g_adst[NN];
__device__ int   g_rowptr[2 * (NN + 1)];
__device__ int   g_cursor[2 * NN];
__device__ int   g_csr_src[2 * EE];
__device__ int   g_bsum[2 * 128];

// ---------------- f32x2 packed-FMA helpers ----------------
__device__ __forceinline__ u64 bcast2(float x) {
    u64 r; asm("mov.b64 %0, {%1, %1};" : "=l"(r) : "f"(x)); return r;
}
__device__ __forceinline__ void fma2(u64& d, u64 a, u64 b) {
    asm("fma.rn.f32x2 %0, %1, %2, %0;" : "+l"(d) : "l"(a), "l"(b));
}
__device__ __forceinline__ float2 unpack2(u64 v) {
    float2 r; asm("mov.b64 {%0, %1}, %2;" : "=f"(r.x), "=f"(r.y) : "l"(v)); return r;
}

// ---------------- GEMM + fused attention dots (f32x2 core) ----------------
template <int K, bool RELU>
__global__ void gemm_att(const float* __restrict__ X, const float* __restrict__ W,
                         float* __restrict__ Y,
                         const float* __restrict__ av_s, const float* __restrict__ av_d,
                         int nrows) {
    __shared__ float xs[64][68];
    __shared__ float ws[64][64];
    __shared__ float redp[16][64];
    __shared__ float redd[16][64];
    int tid = threadIdx.x;
    int tn = (tid & 15) * 4;
    int g  = tid >> 4;
    int tc = g * 4;
    int row0 = blockIdx.x * 64;

    u64 accp[4][2];
#pragma unroll
    for (int i = 0; i < 4; i++) { accp[i][0] = 0ull; accp[i][1] = 0ull; }

    for (int k0 = 0; k0 < K; k0 += 64) {
        for (int idx = tid; idx < 64 * 64; idx += 256) {
            int r = idx >> 6, k = idx & 63;
            int row = row0 + r;
            float v = (row < nrows) ? X[row * K + k0 + k] : 0.f;
            if (RELU) v = fmaxf(v, 0.f);
            xs[k][r] = v;
        }
        for (int idx = tid; idx < 64 * 64; idx += 256) {
            int k = idx >> 6, c = idx & 63;
            ws[k][c] = W[(k0 + k) * 64 + c];
        }
        __syncthreads();
#pragma unroll 8
        for (int kk = 0; kk < 64; ++kk) {
            float4 a = *(const float4*)&xs[kk][tn];
            ulonglong2 bq = *(const ulonglong2*)&ws[kk][tc];
            u64 a0 = bcast2(a.x), a1 = bcast2(a.y), a2 = bcast2(a.z), a3 = bcast2(a.w);
            fma2(accp[0][0], a0, bq.x); fma2(accp[0][1], a0, bq.y);
            fma2(accp[1][0], a1, bq.x); fma2(accp[1][1], a1, bq.y);
            fma2(accp[2][0], a2, bq.x); fma2(accp[2][1], a2, bq.y);
            fma2(accp[3][0], a3, bq.x); fma2(accp[3][1], a3, bq.y);
        }
        __syncthreads();
    }

    float acc[4][4];
#pragma unroll
    for (int i = 0; i < 4; i++) {
        float2 lo = unpack2(accp[i][0]);
        float2 hi = unpack2(accp[i][1]);
        acc[i][0] = lo.x; acc[i][1] = lo.y; acc[i][2] = hi.x; acc[i][3] = hi.y;
    }

    float as0 = av_s[tc], as1 = av_s[tc + 1], as2 = av_s[tc + 2], as3 = av_s[tc + 3];
    float ad0 = av_d[tc], ad1 = av_d[tc + 1], ad2 = av_d[tc + 2], ad3 = av_d[tc + 3];
#pragma unroll
    for (int i = 0; i < 4; i++) {
        int row = row0 + tn + i;
        if (row < nrows) {
            float4 v = make_float4(acc[i][0], acc[i][1], acc[i][2], acc[i][3]);
            *(float4*)&Y[row * 64 + tc] = v;
        }
        redp[g][tn + i] = acc[i][0] * as0 + acc[i][1] * as1 + acc[i][2] * as2 + acc[i][3] * as3;
        redd[g][tn + i] = acc[i][0] * ad0 + acc[i][1] * ad1 + acc[i][2] * ad2 + acc[i][3] * ad3;
    }
    __syncthreads();
    if (tid < 64) {
        int row = row0 + tid;
        float ps = 0.f, pd = 0.f;
#pragma unroll
        for (int c = 0; c < 16; c++) { ps += redp[c][tid]; pd += redd[c][tid]; }
        if (row < nrows) { g_asrc[row] = ps; g_adst[row] = pd; }
    }
}

// ---------------- CSR build ----------------
// hist over BOTH graphs, int2 (2 edges/thread): pair index p in [0, EE).
__global__ void hist2_k(const int* __restrict__ e1, const int* __restrict__ e2) {
    int p = blockIdx.x * blockDim.x + threadIdx.x;
    if (p < EE) {
        int L = (p >= EE / 2);
        const int* e = L ? e2 : e1;
        int lp = p - L * (EE / 2);
        int2 d2 = ((const int2*)(e + EE))[lp];
        atomicAdd(&g_deg[L * NN + d2.x], 1);
        atomicAdd(&g_deg[L * NN + d2.y], 1);
    }
}
__global__ void scan1_k() {
    __shared__ int s[1024];
    int L = blockIdx.y;
    int tid = threadIdx.x;
    int i = blockIdx.x * 1024 + tid;
    int v = (i < NN) ? g_deg[L * NN + i] : 0;
    if (i < NN) g_deg[L * NN + i] = 0;      // reset for next call
    s[tid] = v;
    __syncthreads();
#pragma unroll
    for (int off = 1; off < 1024; off <<= 1) {
        int t = (tid >= off) ? s[tid - off] : 0;
        __syncthreads();
        s[tid] += t;
        __syncthreads();
    }
    if (i < NN) g_rowptr[L * (NN + 1) + i] = s[tid] - v;
    if (tid == 1023) g_bsum[L * 128 + blockIdx.x] = s[1023];
}
__global__ void scan23_k() {
    __shared__ int bpart[128];
    __shared__ int base_s;
    int L = blockIdx.y;
    int b = blockIdx.x;
    int tid = threadIdx.x;
    if (tid < 128) bpart[tid] = (tid < b) ? g_bsum[L * 128 + tid] : 0;
    __syncthreads();
    if (tid < 64) bpart[tid] += bpart[tid + 64];
    __syncthreads();
    if (tid < 32) {
        int v = bpart[tid] + bpart[tid + 32];
#pragma unroll
        for (int off = 16; off; off >>= 1) v += __shfl_xor_sync(0xffffffffu, v, off);
        if (tid == 0) base_s = v;
    }
    __syncthreads();
    int i = b * 1024 + tid;
    if (i < NN) {
        int r = g_rowptr[L * (NN + 1) + i] + base_s;
        g_rowptr[L * (NN + 1) + i] = r;
        g_cursor[L * NN + i] = r;
    }
    if (b == 0 && tid == 0) g_rowptr[L * (NN + 1) + NN] = EE;
}
// per-graph scatter, int2 (2 edges/thread)
__global__ void scatter_k(const int* __restrict__ e, int L) {
    int i = blockIdx.x * blockDim.x + threadIdx.x;
    if (i < EE / 2) {
        int2 d2 = ((const int2*)(e + EE))[i];
        int2 s2 = ((const int2*)e)[i];
        int* cur = g_cursor + L * NN;
        int p0 = atomicAdd(&cur[d2.x], 1);
        g_csr_src[L * EE + p0] = s2.x;
        int p1 = atomicAdd(&cur[d2.y], 1);
        g_csr_src[L * EE + p1] = s2.y;
    }
}

// ---------------- fused segment softmax + aggregate ----------------
template <bool FINAL>
__global__ void agg_k(const float* __restrict__ h, const float* __restrict__ bias,
                      float* __restrict__ out,
                      const int* __restrict__ rowptr, const int* __restrict__ csr,
                      const float* __restrict__ Wl, const float* __restrict__ bl) {
    __shared__ float wsh[64 * 32];
    if (FINAL) {
        for (int i = threadIdx.x; i < 64 * 32; i += 256) wsh[i] = Wl[i];
        __syncthreads();
    }
    int gw = (blockIdx.x * blockDim.x + threadIdx.x) >> 5;
    int lane = threadIdx.x & 31;
    if (gw >= NN) return;
    int half = lane >> 4;
    int q = (lane & 15) * 4;
    int start = rowptr[gw];
    int end = rowptr[gw + 1];
    float ad = g_adst[gw];

    float4 acc = make_float4(0.f, 0.f, 0.f, 0.f);
    float ssum = 0.f;
    for (int j0 = start; j0 < end; j0 += 32) {
        int j = j0 + lane;
        int s = 0; float w = 0.f;
        if (j < end) {
            s = csr[j];
            float e = __ldg(&g_asrc[s]) + ad;
            e = (e >= 0.f) ? e : 0.2f * e;
            w = __expf(e);
        }
        ssum += w;
        int cnt = min(32, end - j0);
        int p2 = 0;
        for (; p2 + 8 <= cnt; p2 += 8) {
            int e0 = p2 + half, e1 = p2 + 2 + half, e2 = p2 + 4 + half, e3 = p2 + 6 + half;
            float w0 = __shfl_sync(0xffffffffu, w, e0);
            int   s0 = __shfl_sync(0xffffffffu, s, e0);
            float w1 = __shfl_sync(0xffffffffu, w, e1);
            int   s1 = __shfl_sync(0xffffffffu, s, e1);
            float w2 = __shfl_sync(0xffffffffu, w, e2);
            int   s2 = __shfl_sync(0xffffffffu, s, e2);
            float w3 = __shfl_sync(0xffffffffu, w, e3);
            int   s3 = __shfl_sync(0xffffffffu, s, e3);
            float4 h0 = *(const float4*)(h + s0 * 64 + q);
            float4 h1 = *(const float4*)(h + s1 * 64 + q);
            float4 h2 = *(const float4*)(h + s2 * 64 + q);
            float4 h3 = *(const float4*)(h + s3 * 64 + q);
            acc.x += w0 * h0.x + w1 * h1.x + w2 * h2.x + w3 * h3.x;
            acc.y += w0 * h0.y + w1 * h1.y + w2 * h2.y + w3 * h3.y;
            acc.z += w0 * h0.z + w1 * h1.z + w2 * h2.z + w3 * h3.z;
            acc.w += w0 * h0.w + w1 * h1.w + w2 * h2.w + w3 * h3.w;
        }
        for (; p2 < cnt; p2 += 2) {
            int ei = p2 + half;
            int eic = (ei < cnt) ? ei : (cnt - 1);
            float wc = __shfl_sync(0xffffffffu, w, eic);
            int   sc = __shfl_sync(0xffffffffu, s, eic);
            if (ei < cnt) {
                float4 hv = *(const float4*)(h + sc * 64 + q);
                acc.x += wc * hv.x; acc.y += wc * hv.y;
                acc.z += wc * hv.z; acc.w += wc * hv.w;
            }
        }
    }
    acc.x += __shfl_xor_sync(0xffffffffu, acc.x, 16);
    acc.y += __shfl_xor_sync(0xffffffffu, acc.y, 16);
    acc.z += __shfl_xor_sync(0xffffffffu, acc.z, 16);
    acc.w += __shfl_xor_sync(0xffffffffu, acc.w, 16);
#pragma unroll
    for (int off = 16; off; off >>= 1) ssum += __shfl_xor_sync(0xffffffffu, ssum, off);
    float inv = 1.0f / (ssum + 1e-16f);

    float4 b4 = *(const float4*)(bias + q);
    float4 o;
    o.x = acc.x * inv + b4.x; o.y = acc.y * inv + b4.y;
    o.z = acc.z * inv + b4.z; o.w = acc.w * inv + b4.w;

    if (!FINAL) {
        if (half == 0) *(float4*)(out + gw * 64 + q) = o;
    } else {
        float oarr[4] = {o.x, o.y, o.z, o.w};
        float accl = __ldg(&bl[lane]);
#pragma unroll
        for (int k = 0; k < 64; k++) {
            float xk = __shfl_sync(0xffffffffu, oarr[k & 3], k >> 2);
            accl += xk * wsh[k * 32 + lane];
        }
        float mx = accl;
#pragma unroll
        for (int off = 16; off; off >>= 1) mx = fmaxf(mx, __shfl_xor_sync(0xffffffffu, mx, off));
        float ex = __expf(accl - mx);
        float sum = ex;
#pragma unroll
        for (int off = 16; off; off >>= 1) sum += __shfl_xor_sync(0xffffffffu, sum, off);
        out[gw * 32 + lane] = accl - mx - __logf(sum);
    }
}

// ---------------- launch: 9 kernels; scatter2 hides under agg1 ----------------
extern "C" void kernel_launch(void* const* d_in, const int* in_sizes, int n_in,
                              void* d_out, int out_size) {
    const float* x    = (const float*)d_in[0];
    const int*   ei1  = (const int*)d_in[1];
    const int*   ei2  = (const int*)d_in[2];
    const float* W1   = (const float*)d_in[3];
    const float* as1  = (const float*)d_in[4];
    const float* ad1  = (const float*)d_in[5];
    const float* b1   = (const float*)d_in[6];
    const float* W2   = (const float*)d_in[7];
    const float* as2  = (const float*)d_in[8];
    const float* ad2  = (const float*)d_in[9];
    const float* b2   = (const float*)d_in[10];
    const float* Wlin = (const float*)d_in[11];
    const float* blin = (const float*)d_in[12];
    float* out = (float*)d_out;

    float *h, *o;
    int *rowptr, *csr;
    cudaGetSymbolAddress((void**)&h, g_h);
    cudaGetSymbolAddress((void**)&o, g_o);
    cudaGetSymbolAddress((void**)&rowptr, g_rowptr);
    cudaGetSymbolAddress((void**)&csr, g_csr_src);

    static cudaStream_t s1 = nullptr;
    static cudaEvent_t ev_fork = nullptr, ev_csr1 = nullptr, ev_csr2 = nullptr;
    if (s1 == nullptr) {
        cudaStreamCreateWithFlags(&s1, cudaStreamNonBlocking);
        cudaEventCreateWithFlags(&ev_fork, cudaEventDisableTiming);
        cudaEventCreateWithFlags(&ev_csr1, cudaEventDisableTiming);
        cudaEventCreateWithFlags(&ev_csr2, cudaEventDisableTiming);
    }

    const int gemm_grid = (NN + 63) / 64;
    const int warp_grid = (NN + 7) / 8;
    const int hgrid = (EE + 255) / 256;          // EE pairs over both graphs
    const int sgrid = (EE / 2 + 255) / 256;      // per-graph pairs

    cudaEventRecord(ev_fork, 0);
    cudaStreamWaitEvent(s1, ev_fork, 0);

    // CSR chain on s1: hist/scan merged over both graphs; scatter split.
    hist2_k<<<hgrid, 256, 0, s1>>>(ei1, ei2);                                 // #1
    scan1_k<<<dim3(NB_SCAN, 2), 1024, 0, s1>>>();                             // #2
    scan23_k<<<dim3(NB_SCAN, 2), 1024, 0, s1>>>();                            // #3
    scatter_k<<<sgrid, 256, 0, s1>>>(ei1, 0);                                 // #4 <- ncu
    cudaEventRecord(ev_csr1, s1);

    // main: gemm1 executes from t0 (independent of s1)
    gemm_att<FIN, false><<<gemm_grid, 256>>>(x, W1, h, as1, ad1, NN);         // #5
    cudaStreamWaitEvent(0, ev_csr1, 0);
    agg_k<false><<<warp_grid, 256>>>(h, b1, o, rowptr, csr, nullptr, nullptr);// #6

    // graph-2 scatter on s1 — executes under agg1
    scatter_k<<<sgrid, 256, 0, s1>>>(ei2, 1);                                 // #7
    cudaEventRecord(ev_csr2, s1);

    gemm_att<HH, true><<<gemm_grid, 256>>>(o, W2, h, as2, ad2, NN);           // #8
    cudaStreamWaitEvent(0, ev_csr2, 0);
    agg_k<true><<<warp_grid, 256>>>(h, b2, out, rowptr + (NN + 1), csr + EE,
                                    Wlin, blin);                              // #9
}

// round 13
// speedup vs baseline: 1.0140x; 1.0140x over previous
#include <cuda_runtime.h>

#define NN 100000
#define EE 1600000
#define FIN 128
#define HH 64
#define OUTF 32
#define NB_SCAN 98   // ceil(100000/1024)

typedef unsigned long long u64;

// ---------------- scratch (device globals; no allocation) ----------------
// g_deg starts zero (static init); scan1_k re-zeroes after consuming.
__device__ int   g_deg[2 * NN];
__device__ float g_h[NN * HH];
__device__ float g_o[NN * HH];
__device__ float g_asrc[NN];
__device__ float g_adst[NN];
__device__ int   g_rowptr[2 * (NN + 1)];
__device__ int   g_cursor[2 * NN];
__device__ int   g_csr_src[2 * EE];
__device__ int   g_bsum[2 * 128];

// ---------------- f32x2 packed-FMA helpers ----------------
__device__ __forceinline__ u64 bcast2(float x) {
    u64 r; asm("mov.b64 %0, {%1, %1};" : "=l"(r) : "f"(x)); return r;
}
__device__ __forceinline__ void fma2(u64& d, u64 a, u64 b) {
    asm("fma.rn.f32x2 %0, %1, %2, %0;" : "+l"(d) : "l"(a), "l"(b));
}
__device__ __forceinline__ float2 unpack2(u64 v) {
    float2 r; asm("mov.b64 {%0, %1}, %2;" : "=f"(r.x), "=f"(r.y) : "l"(v)); return r;
}

// ---------------- GEMM + fused attention dots (f32x2 core) ----------------
template <int K, bool RELU>
__global__ void gemm_att(const float* __restrict__ X, const float* __restrict__ W,
                         float* __restrict__ Y,
                         const float* __restrict__ av_s, const float* __restrict__ av_d,
                         int nrows) {
    __shared__ float xs[64][68];
    __shared__ float ws[64][64];
    __shared__ float redp[16][64];
    __shared__ float redd[16][64];
    int tid = threadIdx.x;
    int tn = (tid & 15) * 4;
    int g  = tid >> 4;
    int tc = g * 4;
    int row0 = blockIdx.x * 64;

    u64 accp[4][2];
#pragma unroll
    for (int i = 0; i < 4; i++) { accp[i][0] = 0ull; accp[i][1] = 0ull; }

    for (int k0 = 0; k0 < K; k0 += 64) {
        for (int idx = tid; idx < 64 * 64; idx += 256) {
            int r = idx >> 6, k = idx & 63;
            int row = row0 + r;
            float v = (row < nrows) ? X[row * K + k0 + k] : 0.f;
            if (RELU) v = fmaxf(v, 0.f);
            xs[k][r] = v;
        }
        for (int idx = tid; idx < 64 * 64; idx += 256) {
            int k = idx >> 6, c = idx & 63;
            ws[k][c] = W[(k0 + k) * 64 + c];
        }
        __syncthreads();
#pragma unroll 8
        for (int kk = 0; kk < 64; ++kk) {
            float4 a = *(const float4*)&xs[kk][tn];
            ulonglong2 bq = *(const ulonglong2*)&ws[kk][tc];
            u64 a0 = bcast2(a.x), a1 = bcast2(a.y), a2 = bcast2(a.z), a3 = bcast2(a.w);
            fma2(accp[0][0], a0, bq.x); fma2(accp[0][1], a0, bq.y);
            fma2(accp[1][0], a1, bq.x); fma2(accp[1][1], a1, bq.y);
            fma2(accp[2][0], a2, bq.x); fma2(accp[2][1], a2, bq.y);
            fma2(accp[3][0], a3, bq.x); fma2(accp[3][1], a3, bq.y);
        }
        __syncthreads();
    }

    float acc[4][4];
#pragma unroll
    for (int i = 0; i < 4; i++) {
        float2 lo = unpack2(accp[i][0]);
        float2 hi = unpack2(accp[i][1]);
        acc[i][0] = lo.x; acc[i][1] = lo.y; acc[i][2] = hi.x; acc[i][3] = hi.y;
    }

    float as0 = av_s[tc], as1 = av_s[tc + 1], as2 = av_s[tc + 2], as3 = av_s[tc + 3];
    float ad0 = av_d[tc], ad1 = av_d[tc + 1], ad2 = av_d[tc + 2], ad3 = av_d[tc + 3];
#pragma unroll
    for (int i = 0; i < 4; i++) {
        int row = row0 + tn + i;
        if (row < nrows) {
            float4 v = make_float4(acc[i][0], acc[i][1], acc[i][2], acc[i][3]);
            *(float4*)&Y[row * 64 + tc] = v;
        }
        redp[g][tn + i] = acc[i][0] * as0 + acc[i][1] * as1 + acc[i][2] * as2 + acc[i][3] * as3;
        redd[g][tn + i] = acc[i][0] * ad0 + acc[i][1] * ad1 + acc[i][2] * ad2 + acc[i][3] * ad3;
    }
    __syncthreads();
    if (tid < 64) {
        int row = row0 + tid;
        float ps = 0.f, pd = 0.f;
#pragma unroll
        for (int c = 0; c < 16; c++) { ps += redp[c][tid]; pd += redd[c][tid]; }
        if (row < nrows) { g_asrc[row] = ps; g_adst[row] = pd; }
    }
}

// ---------------- CSR build ----------------
// hist over BOTH graphs, 1 edge/thread (measured-fast variant).
__global__ void hist2_k(const int* __restrict__ e1, const int* __restrict__ e2) {
    int i = blockIdx.x * blockDim.x + threadIdx.x;   // [0, 2E)
    int L = (i >= EE);
    const int* e = L ? e2 : e1;
    int idx = L ? (i - EE) : i;
    atomicAdd(&g_deg[L * NN + e[EE + idx]], 1);
}
__global__ void scan1_k() {
    __shared__ int s[1024];
    int L = blockIdx.y;
    int tid = threadIdx.x;
    int i = blockIdx.x * 1024 + tid;
    int v = (i < NN) ? g_deg[L * NN + i] : 0;
    if (i < NN) g_deg[L * NN + i] = 0;      // reset for next call
    s[tid] = v;
    __syncthreads();
#pragma unroll
    for (int off = 1; off < 1024; off <<= 1) {
        int t = (tid >= off) ? s[tid - off] : 0;
        __syncthreads();
        s[tid] += t;
        __syncthreads();
    }
    if (i < NN) g_rowptr[L * (NN + 1) + i] = s[tid] - v;
    if (tid == 1023) g_bsum[L * 128 + blockIdx.x] = s[1023];
}
__global__ void scan23_k() {
    __shared__ int bpart[128];
    __shared__ int base_s;
    int L = blockIdx.y;
    int b = blockIdx.x;
    int tid = threadIdx.x;
    if (tid < 128) bpart[tid] = (tid < b) ? g_bsum[L * 128 + tid] : 0;
    __syncthreads();
    if (tid < 64) bpart[tid] += bpart[tid + 64];
    __syncthreads();
    if (tid < 32) {
        int v = bpart[tid] + bpart[tid + 32];
#pragma unroll
        for (int off = 16; off; off >>= 1) v += __shfl_xor_sync(0xffffffffu, v, off);
        if (tid == 0) base_s = v;
    }
    __syncthreads();
    int i = b * 1024 + tid;
    if (i < NN) {
        int r = g_rowptr[L * (NN + 1) + i] + base_s;
        g_rowptr[L * (NN + 1) + i] = r;
        g_cursor[L * NN + i] = r;
    }
    if (b == 0 && tid == 0) g_rowptr[L * (NN + 1) + NN] = EE;
}
// per-graph scatter, 1 edge/thread (measured 17.4us; int2 variant was 24.4us)
__global__ void scatter_k(const int* __restrict__ e, int L) {
    int i = blockIdx.x * blockDim.x + threadIdx.x;
    if (i < EE) {
        int d = e[EE + i];
        int p = atomicAdd(&g_cursor[L * NN + d], 1);
        g_csr_src[L * EE + p] = e[i];
    }
}

// ---------------- fused segment softmax + aggregate ----------------
template <bool FINAL>
__global__ void agg_k(const float* __restrict__ h, const float* __restrict__ bias,
                      float* __restrict__ out,
                      const int* __restrict__ rowptr, const int* __restrict__ csr,
                      const float* __restrict__ Wl, const float* __restrict__ bl) {
    __shared__ float wsh[64 * 32];
    if (FINAL) {
        for (int i = threadIdx.x; i < 64 * 32; i += 256) wsh[i] = Wl[i];
        __syncthreads();
    }
    int gw = (blockIdx.x * blockDim.x + threadIdx.x) >> 5;
    int lane = threadIdx.x & 31;
    if (gw >= NN) return;
    int half = lane >> 4;
    int q = (lane & 15) * 4;
    int start = rowptr[gw];
    int end = rowptr[gw + 1];
    float ad = g_adst[gw];

    float4 acc = make_float4(0.f, 0.f, 0.f, 0.f);
    float ssum = 0.f;
    for (int j0 = start; j0 < end; j0 += 32) {
        int j = j0 + lane;
        int s = 0; float w = 0.f;
        if (j < end) {
            s = csr[j];
            float e = __ldg(&g_asrc[s]) + ad;
            e = (e >= 0.f) ? e : 0.2f * e;
            w = __expf(e);
        }
        ssum += w;
        int cnt = min(32, end - j0);
        int p2 = 0;
        for (; p2 + 8 <= cnt; p2 += 8) {
            int e0 = p2 + half, e1 = p2 + 2 + half, e2 = p2 + 4 + half, e3 = p2 + 6 + half;
            float w0 = __shfl_sync(0xffffffffu, w, e0);
            int   s0 = __shfl_sync(0xffffffffu, s, e0);
            float w1 = __shfl_sync(0xffffffffu, w, e1);
            int   s1 = __shfl_sync(0xffffffffu, s, e1);
            float w2 = __shfl_sync(0xffffffffu, w, e2);
            int   s2 = __shfl_sync(0xffffffffu, s, e2);
            float w3 = __shfl_sync(0xffffffffu, w, e3);
            int   s3 = __shfl_sync(0xffffffffu, s, e3);
            float4 h0 = *(const float4*)(h + s0 * 64 + q);
            float4 h1 = *(const float4*)(h + s1 * 64 + q);
            float4 h2 = *(const float4*)(h + s2 * 64 + q);
            float4 h3 = *(const float4*)(h + s3 * 64 + q);
            acc.x += w0 * h0.x + w1 * h1.x + w2 * h2.x + w3 * h3.x;
            acc.y += w0 * h0.y + w1 * h1.y + w2 * h2.y + w3 * h3.y;
            acc.z += w0 * h0.z + w1 * h1.z + w2 * h2.z + w3 * h3.z;
            acc.w += w0 * h0.w + w1 * h1.w + w2 * h2.w + w3 * h3.w;
        }
        for (; p2 < cnt; p2 += 2) {
            int ei = p2 + half;
            int eic = (ei < cnt) ? ei : (cnt - 1);
            float wc = __shfl_sync(0xffffffffu, w, eic);
            int   sc = __shfl_sync(0xffffffffu, s, eic);
            if (ei < cnt) {
                float4 hv = *(const float4*)(h + sc * 64 + q);
                acc.x += wc * hv.x; acc.y += wc * hv.y;
                acc.z += wc * hv.z; acc.w += wc * hv.w;
            }
        }
    }
    acc.x += __shfl_xor_sync(0xffffffffu, acc.x, 16);
    acc.y += __shfl_xor_sync(0xffffffffu, acc.y, 16);
    acc.z += __shfl_xor_sync(0xffffffffu, acc.z, 16);
    acc.w += __shfl_xor_sync(0xffffffffu, acc.w, 16);
#pragma unroll
    for (int off = 16; off; off >>= 1) ssum += __shfl_xor_sync(0xffffffffu, ssum, off);
    float inv = 1.0f / (ssum + 1e-16f);

    float4 b4 = *(const float4*)(bias + q);
    float4 o;
    o.x = acc.x * inv + b4.x; o.y = acc.y * inv + b4.y;
    o.z = acc.z * inv + b4.z; o.w = acc.w * inv + b4.w;

    if (!FINAL) {
        if (half == 0) *(float4*)(out + gw * 64 + q) = o;
    } else {
        float oarr[4] = {o.x, o.y, o.z, o.w};
        float accl = __ldg(&bl[lane]);
#pragma unroll
        for (int k = 0; k < 64; k++) {
            float xk = __shfl_sync(0xffffffffu, oarr[k & 3], k >> 2);
            accl += xk * wsh[k * 32 + lane];
        }
        float mx = accl;
#pragma unroll
        for (int off = 16; off; off >>= 1) mx = fmaxf(mx, __shfl_xor_sync(0xffffffffu, mx, off));
        float ex = __expf(accl - mx);
        float sum = ex;
#pragma unroll
        for (int off = 16; off; off >>= 1) sum += __shfl_xor_sync(0xffffffffu, sum, off);
        out[gw * 32 + lane] = accl - mx - __logf(sum);
    }
}

// ---------------- launch: 9 kernels; scatter2 hides under agg1 ----------------
extern "C" void kernel_launch(void* const* d_in, const int* in_sizes, int n_in,
                              void* d_out, int out_size) {
    const float* x    = (const float*)d_in[0];
    const int*   ei1  = (const int*)d_in[1];
    const int*   ei2  = (const int*)d_in[2];
    const float* W1   = (const float*)d_in[3];
    const float* as1  = (const float*)d_in[4];
    const float* ad1  = (const float*)d_in[5];
    const float* b1   = (const float*)d_in[6];
    const float* W2   = (const float*)d_in[7];
    const float* as2  = (const float*)d_in[8];
    const float* ad2  = (const float*)d_in[9];
    const float* b2   = (const float*)d_in[10];
    const float* Wlin = (const float*)d_in[11];
    const float* blin = (const float*)d_in[12];
    float* out = (float*)d_out;

    float *h, *o;
    int *rowptr, *csr;
    cudaGetSymbolAddress((void**)&h, g_h);
    cudaGetSymbolAddress((void**)&o, g_o);
    cudaGetSymbolAddress((void**)&rowptr, g_rowptr);
    cudaGetSymbolAddress((void**)&csr, g_csr_src);

    static cudaStream_t s1 = nullptr;
    static cudaEvent_t ev_fork = nullptr, ev_csr1 = nullptr, ev_csr2 = nullptr;
    if (s1 == nullptr) {
        cudaStreamCreateWithFlags(&s1, cudaStreamNonBlocking);
        cudaEventCreateWithFlags(&ev_fork, cudaEventDisableTiming);
        cudaEventCreateWithFlags(&ev_csr1, cudaEventDisableTiming);
        cudaEventCreateWithFlags(&ev_csr2, cudaEventDisableTiming);
    }

    const int gemm_grid = (NN + 63) / 64;
    const int warp_grid = (NN + 7) / 8;
    const int hgrid = 2 * EE / 256;      // both graphs, 1 edge/thread
    const int sgrid = EE / 256;          // per-graph, 1 edge/thread

    cudaEventRecord(ev_fork, 0);
    cudaStreamWaitEvent(s1, ev_fork, 0);

    // CSR chain on s1: hist/scan merged over both graphs; scatter split per graph.
    hist2_k<<<hgrid, 256, 0, s1>>>(ei1, ei2);                                 // #1
    scan1_k<<<dim3(NB_SCAN, 2), 1024, 0, s1>>>();                             // #2
    scan23_k<<<dim3(NB_SCAN, 2), 1024, 0, s1>>>();                            // #3
    scatter_k<<<sgrid, 256, 0, s1>>>(ei1, 0);                                 // #4 <- ncu
    cudaEventRecord(ev_csr1, s1);

    // main: gemm1 executes from t0 (independent of s1)
    gemm_att<FIN, false><<<gemm_grid, 256>>>(x, W1, h, as1, ad1, NN);         // #5
    cudaStreamWaitEvent(0, ev_csr1, 0);
    agg_k<false><<<warp_grid, 256>>>(h, b1, o, rowptr, csr, nullptr, nullptr);// #6

    // graph-2 scatter on s1 — executes under agg1
    scatter_k<<<sgrid, 256, 0, s1>>>(ei2, 1);                                 // #7
    cudaEventRecord(ev_csr2, s1);

    gemm_att<HH, true><<<gemm_grid, 256>>>(o, W2, h, as2, ad2, NN);           // #8
    cudaStreamWaitEvent(0, ev_csr2, 0);
    agg_k<true><<<warp_grid, 256>>>(h, b2, out, rowptr + (NN + 1), csr + EE,
                                    Wlin, blin);                              // #9
}

// round 14
// speedup vs baseline: 1.1187x; 1.1032x over previous
#include <cuda_runtime.h>

#define NN 100000
#define EE 1600000
#define FIN 128
#define HH 64
#define OUTF 32
#define NB_SCAN 98   // ceil(100000/1024)

typedef unsigned long long u64;

// ---------------- scratch (device globals; no allocation) ----------------
// g_deg starts zero (static init); scan1_k re-zeroes after consuming.
__device__ int   g_deg[2 * NN];
__device__ float g_h[NN * HH];
__device__ float g_o[NN * HH];
__device__ float g_asrc[NN];
__device__ float g_adst[NN];
__device__ int   g_rowptr[2 * (NN + 1)];
__device__ int   g_cursor[2 * NN];
__device__ int   g_csr_src[2 * EE];
__device__ int   g_bsum[2 * 128];

// ---------------- f32x2 packed-FMA helpers ----------------
__device__ __forceinline__ u64 bcast2(float x) {
    u64 r; asm("mov.b64 %0, {%1, %1};" : "=l"(r) : "f"(x)); return r;
}
__device__ __forceinline__ void fma2(u64& d, u64 a, u64 b) {
    asm("fma.rn.f32x2 %0, %1, %2, %0;" : "+l"(d) : "l"(a), "l"(b));
}
__device__ __forceinline__ float2 unpack2(u64 v) {
    float2 r; asm("mov.b64 {%0, %1}, %2;" : "=f"(r.x), "=f"(r.y) : "l"(v)); return r;
}

// ---------------- GEMM + fused attention dots ----------------
// Tile: 128 rows x 64 cols, K-chunk 32. Warp g owns cols [8g, 8g+8);
// all B reads are warp-uniform (LDS broadcast). 4 rows x 8 cols per thread.
template <int K, bool RELU>
__global__ void __launch_bounds__(256) gemm_att(
        const float* __restrict__ X, const float* __restrict__ W,
        float* __restrict__ Y,
        const float* __restrict__ av_s, const float* __restrict__ av_d) {
    __shared__ float xs[32][132];    // [k][row], padded (132*4B = 16B-aligned rows)
    __shared__ float ws[32][64];     // [k][col]
    __shared__ float redp[8][128];
    __shared__ float redd[8][128];
    int tid = threadIdx.x;
    int tn = (tid & 31) * 4;         // row offset 0..124
    int g  = tid >> 5;               // warp index = colgroup 0..7
    int tc = g * 8;                  // col offset
    int row0 = blockIdx.x * 128;

    u64 acc[4][4];                   // [row i][col-pair j] -> cols tc+2j, tc+2j+1
#pragma unroll
    for (int i = 0; i < 4; i++)
#pragma unroll
        for (int j = 0; j < 4; j++) acc[i][j] = 0ull;

    for (int k0 = 0; k0 < K; k0 += 32) {
        for (int idx = tid; idx < 128 * 32; idx += 256) {
            int r = idx >> 5, k = idx & 31;
            int row = row0 + r;
            float v = (row < NN) ? X[row * K + k0 + k] : 0.f;
            if (RELU) v = fmaxf(v, 0.f);
            xs[k][r] = v;
        }
        for (int idx = tid; idx < 32 * 64; idx += 256) {
            int k = idx >> 6, c = idx & 63;
            ws[k][c] = W[(k0 + k) * 64 + c];
        }
        __syncthreads();
#pragma unroll 8
        for (int kk = 0; kk < 32; ++kk) {
            float4 a = *(const float4*)&xs[kk][tn];
            ulonglong2 b0 = *(const ulonglong2*)&ws[kk][tc];       // cols tc..tc+3
            ulonglong2 b1 = *(const ulonglong2*)&ws[kk][tc + 4];   // cols tc+4..tc+7
            u64 A0 = bcast2(a.x), A1 = bcast2(a.y), A2 = bcast2(a.z), A3 = bcast2(a.w);
            fma2(acc[0][0], A0, b0.x); fma2(acc[0][1], A0, b0.y);
            fma2(acc[0][2], A0, b1.x); fma2(acc[0][3], A0, b1.y);
            fma2(acc[1][0], A1, b0.x); fma2(acc[1][1], A1, b0.y);
            fma2(acc[1][2], A1, b1.x); fma2(acc[1][3], A1, b1.y);
            fma2(acc[2][0], A2, b0.x); fma2(acc[2][1], A2, b0.y);
            fma2(acc[2][2], A2, b1.x); fma2(acc[2][3], A2, b1.y);
            fma2(acc[3][0], A3, b0.x); fma2(acc[3][1], A3, b0.y);
            fma2(acc[3][2], A3, b1.x); fma2(acc[3][3], A3, b1.y);
        }
        __syncthreads();
    }

    float avs[8], avd[8];
#pragma unroll
    for (int j = 0; j < 8; j++) { avs[j] = av_s[tc + j]; avd[j] = av_d[tc + j]; }

#pragma unroll
    for (int i = 0; i < 4; i++) {
        int row = row0 + tn + i;
        float c[8];
#pragma unroll
        for (int j = 0; j < 4; j++) {
            float2 p = unpack2(acc[i][j]);
            c[2 * j] = p.x; c[2 * j + 1] = p.y;
        }
        if (row < NN) {
            *(float4*)&Y[row * 64 + tc]     = make_float4(c[0], c[1], c[2], c[3]);
            *(float4*)&Y[row * 64 + tc + 4] = make_float4(c[4], c[5], c[6], c[7]);
        }
        float ps = 0.f, pd = 0.f;
#pragma unroll
        for (int j = 0; j < 8; j++) { ps += c[j] * avs[j]; pd += c[j] * avd[j]; }
        redp[g][tn + i] = ps;
        redd[g][tn + i] = pd;
    }
    __syncthreads();
    if (tid < 128) {
        int row = row0 + tid;
        float ps = 0.f, pd = 0.f;
#pragma unroll
        for (int c = 0; c < 8; c++) { ps += redp[c][tid]; pd += redd[c][tid]; }
        if (row < NN) { g_asrc[row] = ps; g_adst[row] = pd; }
    }
}

// ---------------- CSR build (per-graph chains) ----------------
__global__ void hist_k(const int* __restrict__ e, int L) {
    int i = blockIdx.x * blockDim.x + threadIdx.x;
    if (i < EE) atomicAdd(&g_deg[L * NN + e[EE + i]], 1);
}
__global__ void scan1_k(int L) {
    __shared__ int s[1024];
    int tid = threadIdx.x;
    int i = blockIdx.x * 1024 + tid;
    int v = (i < NN) ? g_deg[L * NN + i] : 0;
    if (i < NN) g_deg[L * NN + i] = 0;      // reset for next call
    s[tid] = v;
    __syncthreads();
#pragma unroll
    for (int off = 1; off < 1024; off <<= 1) {
        int t = (tid >= off) ? s[tid - off] : 0;
        __syncthreads();
        s[tid] += t;
        __syncthreads();
    }
    if (i < NN) g_rowptr[L * (NN + 1) + i] = s[tid] - v;
    if (tid == 1023) g_bsum[L * 128 + blockIdx.x] = s[1023];
}
__global__ void scan23_k(int L) {
    __shared__ int bpart[128];
    __shared__ int base_s;
    int b = blockIdx.x;
    int tid = threadIdx.x;
    if (tid < 128) bpart[tid] = (tid < b) ? g_bsum[L * 128 + tid] : 0;
    __syncthreads();
    if (tid < 64) bpart[tid] += bpart[tid + 64];
    __syncthreads();
    if (tid < 32) {
        int v = bpart[tid] + bpart[tid + 32];
#pragma unroll
        for (int off = 16; off; off >>= 1) v += __shfl_xor_sync(0xffffffffu, v, off);
        if (tid == 0) base_s = v;
    }
    __syncthreads();
    int i = b * 1024 + tid;
    if (i < NN) {
        int r = g_rowptr[L * (NN + 1) + i] + base_s;
        g_rowptr[L * (NN + 1) + i] = r;
        g_cursor[L * NN + i] = r;
    }
    if (b == 0 && tid == 0) g_rowptr[L * (NN + 1) + NN] = EE;
}
__global__ void scatter_k(const int* __restrict__ e, int L) {
    int i = blockIdx.x * blockDim.x + threadIdx.x;
    if (i < EE) {
        int d = e[EE + i];
        int p = atomicAdd(&g_cursor[L * NN + d], 1);
        g_csr_src[L * EE + p] = e[i];
    }
}

// ---------------- fused segment softmax + aggregate ----------------
template <bool FINAL>
__global__ void __launch_bounds__(256, 6) agg_k(
        const float* __restrict__ h, const float* __restrict__ bias,
        float* __restrict__ out,
        const int* __restrict__ rowptr, const int* __restrict__ csr,
        const float* __restrict__ Wl, const float* __restrict__ bl) {
    __shared__ float wsh[64 * 32];
    if (FINAL) {
        for (int i = threadIdx.x; i < 64 * 32; i += 256) wsh[i] = Wl[i];
        __syncthreads();
    }
    int gw = (blockIdx.x * blockDim.x + threadIdx.x) >> 5;
    int lane = threadIdx.x & 31;
    if (gw >= NN) return;
    int half = lane >> 4;
    int q = (lane & 15) * 4;
    int start = rowptr[gw];
    int end = rowptr[gw + 1];
    float ad = g_adst[gw];

    float4 acc = make_float4(0.f, 0.f, 0.f, 0.f);
    float ssum = 0.f;
    for (int j0 = start; j0 < end; j0 += 32) {
        int j = j0 + lane;
        int s = 0; float w = 0.f;
        if (j < end) {
            s = csr[j];
            float e = __ldg(&g_asrc[s]) + ad;
            e = (e >= 0.f) ? e : 0.2f * e;
            w = __expf(e);
        }
        ssum += w;
        int cnt = min(32, end - j0);
        int p2 = 0;
        for (; p2 + 8 <= cnt; p2 += 8) {
            int e0 = p2 + half, e1 = p2 + 2 + half, e2 = p2 + 4 + half, e3 = p2 + 6 + half;
            float w0 = __shfl_sync(0xffffffffu, w, e0);
            int   s0 = __shfl_sync(0xffffffffu, s, e0);
            float w1 = __shfl_sync(0xffffffffu, w, e1);
            int   s1 = __shfl_sync(0xffffffffu, s, e1);
            float w2 = __shfl_sync(0xffffffffu, w, e2);
            int   s2 = __shfl_sync(0xffffffffu, s, e2);
            float w3 = __shfl_sync(0xffffffffu, w, e3);
            int   s3 = __shfl_sync(0xffffffffu, s, e3);
            float4 h0 = *(const float4*)(h + s0 * 64 + q);
            float4 h1 = *(const float4*)(h + s1 * 64 + q);
            float4 h2 = *(const float4*)(h + s2 * 64 + q);
            float4 h3 = *(const float4*)(h + s3 * 64 + q);
            acc.x += w0 * h0.x + w1 * h1.x + w2 * h2.x + w3 * h3.x;
            acc.y += w0 * h0.y + w1 * h1.y + w2 * h2.y + w3 * h3.y;
            acc.z += w0 * h0.z + w1 * h1.z + w2 * h2.z + w3 * h3.z;
            acc.w += w0 * h0.w + w1 * h1.w + w2 * h2.w + w3 * h3.w;
        }
        for (; p2 < cnt; p2 += 2) {
            int ei = p2 + half;
            int eic = (ei < cnt) ? ei : (cnt - 1);
            float wc = __shfl_sync(0xffffffffu, w, eic);
            int   sc = __shfl_sync(0xffffffffu, s, eic);
            if (ei < cnt) {
                float4 hv = *(const float4*)(h + sc * 64 + q);
                acc.x += wc * hv.x; acc.y += wc * hv.y;
                acc.z += wc * hv.z; acc.w += wc * hv.w;
            }
        }
    }
    acc.x += __shfl_xor_sync(0xffffffffu, acc.x, 16);
    acc.y += __shfl_xor_sync(0xffffffffu, acc.y, 16);
    acc.z += __shfl_xor_sync(0xffffffffu, acc.z, 16);
    acc.w += __shfl_xor_sync(0xffffffffu, acc.w, 16);
#pragma unroll
    for (int off = 16; off; off >>= 1) ssum += __shfl_xor_sync(0xffffffffu, ssum, off);
    float inv = 1.0f / (ssum + 1e-16f);

    float4 b4 = *(const float4*)(bias + q);
    float4 o;
    o.x = acc.x * inv + b4.x; o.y = acc.y * inv + b4.y;
    o.z = acc.z * inv + b4.z; o.w = acc.w * inv + b4.w;

    if (!FINAL) {
        if (half == 0) *(float4*)(out + gw * 64 + q) = o;
    } else {
        float oarr[4] = {o.x, o.y, o.z, o.w};
        float accl = __ldg(&bl[lane]);
#pragma unroll
        for (int k = 0; k < 64; k++) {
            float xk = __shfl_sync(0xffffffffu, oarr[k & 3], k >> 2);
            accl += xk * wsh[k * 32 + lane];
        }
        float mx = accl;
#pragma unroll
        for (int off = 16; off; off >>= 1) mx = fmaxf(mx, __shfl_xor_sync(0xffffffffu, mx, off));
        float ex = __expf(accl - mx);
        float sum = ex;
#pragma unroll
        for (int off = 16; off; off >>= 1) sum += __shfl_xor_sync(0xffffffffu, sum, off);
        out[gw * 32 + lane] = accl - mx - __logf(sum);
    }
}

// ---------------- launch: per-graph chains; chain2 hides under agg1 ----------
extern "C" void kernel_launch(void* const* d_in, const int* in_sizes, int n_in,
                              void* d_out, int out_size) {
    const float* x    = (const float*)d_in[0];
    const int*   ei1  = (const int*)d_in[1];
    const int*   ei2  = (const int*)d_in[2];
    const float* W1   = (const float*)d_in[3];
    const float* as1  = (const float*)d_in[4];
    const float* ad1  = (const float*)d_in[5];
    const float* b1   = (const float*)d_in[6];
    const float* W2   = (const float*)d_in[7];
    const float* as2  = (const float*)d_in[8];
    const float* ad2  = (const float*)d_in[9];
    const float* b2   = (const float*)d_in[10];
    const float* Wlin = (const float*)d_in[11];
    const float* blin = (const float*)d_in[12];
    float* out = (float*)d_out;

    float *h, *o;
    int *rowptr, *csr;
    cudaGetSymbolAddress((void**)&h, g_h);
    cudaGetSymbolAddress((void**)&o, g_o);
    cudaGetSymbolAddress((void**)&rowptr, g_rowptr);
    cudaGetSymbolAddress((void**)&csr, g_csr_src);

    static cudaStream_t s1 = nullptr;
    static cudaEvent_t ev_fork = nullptr, ev_csr1 = nullptr, ev_csr2 = nullptr;
    if (s1 == nullptr) {
        cudaStreamCreateWithFlags(&s1, cudaStreamNonBlocking);
        cudaEventCreateWithFlags(&ev_fork, cudaEventDisableTiming);
        cudaEventCreateWithFlags(&ev_csr1, cudaEventDisableTiming);
        cudaEventCreateWithFlags(&ev_csr2, cudaEventDisableTiming);
    }

    const int gemm_grid = (NN + 127) / 128;   // 782
    const int warp_grid = (NN + 7) / 8;       // 12500
    const int egrid = EE / 256;

    cudaEventRecord(ev_fork, 0);
    cudaStreamWaitEvent(s1, ev_fork, 0);

    // chain1 (graph 1) on s1 — overlaps gemm1
    hist_k<<<egrid, 256, 0, s1>>>(ei1, 0);                                    // #1
    scan1_k<<<NB_SCAN, 1024, 0, s1>>>(0);                                     // #2
    scan23_k<<<NB_SCAN, 1024, 0, s1>>>(0);                                    // #3
    scatter_k<<<egrid, 256, 0, s1>>>(ei1, 0);                                 // #4 <- ncu
    cudaEventRecord(ev_csr1, s1);

    // main: gemm1 executes from t0
    gemm_att<FIN, false><<<gemm_grid, 256>>>(x, W1, h, as1, ad1);             // #5
    cudaStreamWaitEvent(0, ev_csr1, 0);
    agg_k<false><<<warp_grid, 256>>>(h, b1, o, rowptr, csr, nullptr, nullptr);// #6

    // chain2 (graph 2) on s1 — executes under agg1 + gemm2
    hist_k<<<egrid, 256, 0, s1>>>(ei2, 1);                                    // #7
    scan1_k<<<NB_SCAN, 1024, 0, s1>>>(1);                                     // #8
    scan23_k<<<NB_SCAN, 1024, 0, s1>>>(1);                                    // #9
    scatter_k<<<egrid, 256, 0, s1>>>(ei2, 1);                                 // #10
    cudaEventRecord(ev_csr2, s1);

    gemm_att<HH, true><<<gemm_grid, 256>>>(o, W2, h, as2, ad2);               // #11
    cudaStreamWaitEvent(0, ev_csr2, 0);
    agg_k<true><<<warp_grid, 256>>>(h, b2, out, rowptr + (NN + 1), csr + EE,
                                    Wlin, blin);                              // #12
}